// round 7
// baseline (speedup 1.0000x reference)
#include <cuda_runtime.h>
#include <cstdint>

#define BSZ 2
#define SEQ 2048
#define DIM 1024
#define NHEAD 16
#define HDIM 64
#define MROWS (BSZ * SEQ)   // 4096

// Scratch (allocation-free requirement -> __device__ globals).
__device__ float g_q[(size_t)BSZ * SEQ * DIM];
__device__ float g_k[(size_t)BSZ * SEQ * DIM];
__device__ float g_v[(size_t)BSZ * SEQ * DIM];
__device__ float g_ctx[(size_t)BSZ * SEQ * DIM];
__device__ float g_wr[(size_t)4 * DIM * DIM];   // tf32-rounded weights

// 0.125 (1/sqrt(64)) * log2(e): Q pre-scale so softmax can use exp2.
#define QSCALE 0.1803368801111137f

__device__ __forceinline__ float to_tf32(float x) {
    float r;
    asm("cvt.rna.tf32.f32 %0, %1;" : "=f"(r) : "f"(x));
    return r;
}

__device__ __forceinline__ uint32_t smem_u32(const void* p) {
    uint32_t a;
    asm("{ .reg .u64 t; cvta.to.shared.u64 t, %1; cvt.u32.u64 %0, t; }"
        : "=r"(a) : "l"(p));
    return a;
}

__device__ __forceinline__ void cp_async16(uint32_t dst, const void* src) {
    asm volatile("cp.async.cg.shared.global [%0], [%1], 16;"
                 :: "r"(dst), "l"(src));
}
#define CP_COMMIT() asm volatile("cp.async.commit_group;" ::: "memory")
#define CP_WAIT0()  asm volatile("cp.async.wait_group 0;" ::: "memory")
#define CP_WAIT1()  asm volatile("cp.async.wait_group 1;" ::: "memory")

// m16n8k8 tf32 HMMA. A row-major 16x8, B col-major 8x8, C 16x8 fp32.
__device__ __forceinline__ void mma_tf32(float c[4],
                                         uint32_t a0, uint32_t a1,
                                         uint32_t a2, uint32_t a3,
                                         uint32_t b0, uint32_t b1) {
    asm volatile(
        "mma.sync.aligned.m16n8k8.row.col.f32.tf32.tf32.f32 "
        "{%0,%1,%2,%3}, {%4,%5,%6,%7}, {%8,%9}, {%0,%1,%2,%3};"
        : "+f"(c[0]), "+f"(c[1]), "+f"(c[2]), "+f"(c[3])
        : "r"(a0), "r"(a1), "r"(a2), "r"(a3), "r"(b0), "r"(b1));
}

// ---------------------------------------------------------------------------
// Weight pre-round: g_wr[z] = tf32(W[z]) elementwise.
// ---------------------------------------------------------------------------
__global__ __launch_bounds__(256) void round_w_kernel(
    const float* __restrict__ Wq, const float* __restrict__ Wk,
    const float* __restrict__ Wv, const float* __restrict__ Wo)
{
    const int z = blockIdx.y;
    const float* src = (z == 0) ? Wq : (z == 1) ? Wk : (z == 2) ? Wv : Wo;
    float* dst = g_wr + (size_t)z * DIM * DIM;
    size_t off = ((size_t)blockIdx.x * 256 + threadIdx.x) * 4;
    float4 v = *(const float4*)(src + off);
    v.x = to_tf32(v.x); v.y = to_tf32(v.y);
    v.z = to_tf32(v.z); v.w = to_tf32(v.w);
    *(float4*)(dst + off) = v;
}

// ---------------------------------------------------------------------------
// GEMM: C[4096,1024] = (A @ W + bias) * scale, HMMA tf32, cp.async 3-stage,
// ONE barrier per chunk (prefetch at chunk ch targets stage (ch-1)%3 whose
// readers already passed this chunk's top barrier).
// ---------------------------------------------------------------------------
#define PA 36
#define PB 136
#define SOFF_B (128 * PA)                    // 4608 floats
#define STAGE_FLOATS (128 * PA + 32 * PB)    // 8960
#define OFF_BIAS (3 * STAGE_FLOATS)          // 26880
#define GEMM_SMEM_BYTES ((OFF_BIAS + 128) * 4)   // 108032

__device__ __forceinline__ void gemm_issue(
    uint32_t sbase, int s, int ch, const float* __restrict__ A,
    const float* __restrict__ W, int m0, int n0, int tid)
{
    uint32_t sa = sbase + (uint32_t)(s * STAGE_FLOATS) * 4u;
    uint32_t sb = sa + SOFF_B * 4u;
    const float* Ap = A + (size_t)m0 * DIM + ch * 32;
    const float* Wp = W + (size_t)ch * 32 * DIM + n0;
#pragma unroll
    for (int u = 0; u < 4; ++u) {
        int i = tid + u * 256;
        int ar = i >> 3, ac = (i & 7) << 2;
        cp_async16(sa + (uint32_t)(ar * PA + ac) * 4u,
                   Ap + (size_t)ar * DIM + ac);
        int br = i >> 5, bc = (i & 31) << 2;
        cp_async16(sb + (uint32_t)(br * PB + bc) * 4u,
                   Wp + (size_t)br * DIM + bc);
    }
}

template <bool RA, bool RO>
__device__ __forceinline__ void gemm_body(
    const float* __restrict__ A, const float* __restrict__ W,
    const float* __restrict__ bias, float* __restrict__ C, float scale,
    float* sm)
{
    const uint32_t sbase = smem_u32(sm);
    const int tid = threadIdx.x;
    const int wid = tid >> 5, lane = tid & 31;
    const int wm = wid >> 2, wn = wid & 3;
    const int g = lane >> 2, tig = lane & 3;
    const int n0 = blockIdx.x * 128;
    const int m0 = blockIdx.y * 128;

    if (tid < 128) sm[OFF_BIAS + tid] = bias[n0 + tid];

    float c[4][4][4];
#pragma unroll
    for (int mt = 0; mt < 4; ++mt)
#pragma unroll
        for (int nt = 0; nt < 4; ++nt)
#pragma unroll
            for (int q = 0; q < 4; ++q) c[mt][nt][q] = 0.f;

    gemm_issue(sbase, 0, 0, A, W, m0, n0, tid);
    CP_COMMIT();
    gemm_issue(sbase, 1, 1, A, W, m0, n0, tid);
    CP_COMMIT();

    for (int ch = 0; ch < 32; ++ch) {
        if (ch == 31) CP_WAIT0(); else CP_WAIT1();
        __syncthreads();
        if (ch < 30) {
            gemm_issue(sbase, (ch + 2) % 3, ch + 2, A, W, m0, n0, tid);
            CP_COMMIT();
        }

        const uint32_t* sA = (const uint32_t*)(sm + (ch % 3) * STAGE_FLOATS);
        const uint32_t* sB = sA + SOFF_B;

#pragma unroll
        for (int kk = 0; kk < 4; ++kk) {
            uint32_t af[4][4], bf[4][2];
#pragma unroll
            for (int mt = 0; mt < 4; ++mt) {
                int r0 = wm * 64 + mt * 16 + g;
                af[mt][0] = sA[r0 * PA + kk * 8 + tig];
                af[mt][1] = sA[(r0 + 8) * PA + kk * 8 + tig];
                af[mt][2] = sA[r0 * PA + kk * 8 + tig + 4];
                af[mt][3] = sA[(r0 + 8) * PA + kk * 8 + tig + 4];
                if (RA) {
#pragma unroll
                    for (int q = 0; q < 4; ++q)
                        af[mt][q] = __float_as_uint(
                            to_tf32(__uint_as_float(af[mt][q])));
                }
            }
#pragma unroll
            for (int nt = 0; nt < 4; ++nt) {
                int cb = wn * 32 + nt * 8 + g;
                bf[nt][0] = sB[(kk * 8 + tig) * PB + cb];
                bf[nt][1] = sB[(kk * 8 + tig + 4) * PB + cb];
            }
#pragma unroll
            for (int mt = 0; mt < 4; ++mt)
#pragma unroll
                for (int nt = 0; nt < 4; ++nt)
                    mma_tf32(c[mt][nt], af[mt][0], af[mt][1], af[mt][2],
                             af[mt][3], bf[nt][0], bf[nt][1]);
        }
        // No trailing barrier: next chunk's top barrier orders the next
        // prefetch (into stage ch%3) after all warps finish reading it here.
    }

#pragma unroll
    for (int mt = 0; mt < 4; ++mt) {
        int row = m0 + wm * 64 + mt * 16 + g;
#pragma unroll
        for (int nt = 0; nt < 4; ++nt) {
            int col = wn * 32 + nt * 8 + 2 * tig;
            float b0 = sm[OFF_BIAS + col], b1 = sm[OFF_BIAS + col + 1];
            float v00 = (c[mt][nt][0] + b0) * scale;
            float v01 = (c[mt][nt][1] + b1) * scale;
            float v10 = (c[mt][nt][2] + b0) * scale;
            float v11 = (c[mt][nt][3] + b1) * scale;
            if (RO) {
                v00 = to_tf32(v00); v01 = to_tf32(v01);
                v10 = to_tf32(v10); v11 = to_tf32(v11);
            }
            *(float2*)(C + (size_t)row * DIM + n0 + col) =
                make_float2(v00, v01);
            *(float2*)(C + (size_t)(row + 8) * DIM + n0 + col) =
                make_float2(v10, v11);
        }
    }
}

// Batched QKV projection: grid.z picks (A, bias, out, scale); W from g_wr.
__global__ __launch_bounds__(256, 2) void qkv_gemm_kernel(
    const float* __restrict__ Q, const float* __restrict__ K,
    const float* __restrict__ V,
    const float* __restrict__ bq, const float* __restrict__ bk,
    const float* __restrict__ bv)
{
    extern __shared__ float sm[];
    const int z = blockIdx.z;
    const float* A = (z == 0) ? Q : (z == 1) ? K : V;
    const float* W = g_wr + (size_t)z * DIM * DIM;
    const float* bias = (z == 0) ? bq : (z == 1) ? bk : bv;
    float* C = (z == 0) ? g_q : (z == 1) ? g_k : g_v;
    float scale = (z == 0) ? QSCALE : 1.0f;
    gemm_body<true, true>(A, W, bias, C, scale, sm);
}

// Output projection: A (g_ctx) already tf32-rounded, output fp32.
__global__ __launch_bounds__(256, 2) void oproj_gemm_kernel(
    const float* __restrict__ bias, float* __restrict__ C)
{
    extern __shared__ float sm[];
    gemm_body<false, false>(g_ctx, g_wr + (size_t)3 * DIM * DIM, bias, C,
                            1.0f, sm);
}

// ---------------------------------------------------------------------------
// FA2-style attention: block = 128 q rows x one head x one batch, 8 warps.
// Warp owns 16 q rows x 64 keys/tile. S/P/m/l/O in registers; P->A-frag via
// quad shuffles. K/V double-buffered via cp.async. Mask LDGs hoisted to tile
// top (before the cp.async wait) and packed into one register.
// ---------------------------------------------------------------------------
#define AQP 68
#define AVP 72
#define Q_FLOATS (128 * AQP)                 // 8704
#define KV_AOFF_V (64 * AQP)                 // 4352
#define KV_STAGE (64 * AQP + 64 * AVP)       // 8960
#define ATTN_SMEM_BYTES ((Q_FLOATS + 2 * KV_STAGE) * 4)   // 106496

__global__ __launch_bounds__(256, 2) void attn_mma_kernel(
    const int* __restrict__ mask, float* __restrict__ ctx)
{
    extern __shared__ float sm[];
    const uint32_t sbase = smem_u32(sm);
    float* Qs = sm;

    const int tid = threadIdx.x;
    const int wid = tid >> 5, lane = tid & 31;
    const int g = lane >> 2, tig = lane & 3;
    const int q0 = blockIdx.x * 128;
    const int h = blockIdx.y;
    const int b = blockIdx.z;

    const float* qb = g_q + ((size_t)b * SEQ + q0) * DIM + h * HDIM;
    const float* kb = g_k + (size_t)b * SEQ * DIM + h * HDIM;
    const float* vb = g_v + (size_t)b * SEQ * DIM + h * HDIM;

    // Prologue: async-stage Q tile + KV tile 0 as one group.
#pragma unroll
    for (int u = 0; u < 8; ++u) {
        int i = tid + u * 256;
        int row = i >> 4, c4 = (i & 15) << 2;
        cp_async16(sbase + (uint32_t)(row * AQP + c4) * 4u,
                   qb + (size_t)row * DIM + c4);
    }
    {
        uint32_t kst = sbase + Q_FLOATS * 4u;
        uint32_t vst = kst + KV_AOFF_V * 4u;
#pragma unroll
        for (int u = 0; u < 4; ++u) {
            int i = tid + u * 256;
            int row = i >> 4, c4 = (i & 15) << 2;
            cp_async16(kst + (uint32_t)(row * AQP + c4) * 4u,
                       kb + (size_t)row * DIM + c4);
            cp_async16(vst + (uint32_t)(row * AVP + c4) * 4u,
                       vb + (size_t)row * DIM + c4);
        }
    }
    CP_COMMIT();

    const int r0 = wid * 16 + g;
    float m0 = -1e30f, m1 = -1e30f, l0 = 0.f, l1 = 0.f;
    float o[8][4];
#pragma unroll
    for (int nt = 0; nt < 8; ++nt)
#pragma unroll
        for (int q = 0; q < 4; ++q) o[nt][q] = 0.f;

    const int* mbase0 = mask + (size_t)(q0 + r0) * SEQ + 2 * tig;
    const int* mbase1 = mbase0 + 8 * SEQ;

    for (int kt = 0; kt < SEQ / 64; ++kt) {
        const int kg0 = kt * 64;

        // Hoisted mask loads (no SMEM dependence): pack 32 bits now, LDG
        // latency hides behind cp.async wait + S-MMA phase.
        uint32_t mbits = 0;
#pragma unroll
        for (int nt = 0; nt < 8; ++nt) {
            int2 ma = *(const int2*)(mbase0 + kg0 + nt * 8);
            int2 mb = *(const int2*)(mbase1 + kg0 + nt * 8);
            uint32_t nib = (ma.x ? 1u : 0u) | (ma.y ? 2u : 0u) |
                           (mb.x ? 4u : 0u) | (mb.y ? 8u : 0u);
            mbits |= nib << (nt * 4);
        }

        CP_WAIT0();
        __syncthreads();

        // Prefetch next KV tile into the other stage.
        if (kt < SEQ / 64 - 1) {
            int s = (kt + 1) & 1;
            int kg = (kt + 1) * 64;
            uint32_t kst = sbase + (uint32_t)(Q_FLOATS + s * KV_STAGE) * 4u;
            uint32_t vst = kst + KV_AOFF_V * 4u;
#pragma unroll
            for (int u = 0; u < 4; ++u) {
                int i = tid + u * 256;
                int row = i >> 4, c4 = (i & 15) << 2;
                cp_async16(kst + (uint32_t)(row * AQP + c4) * 4u,
                           kb + (size_t)(kg + row) * DIM + c4);
                cp_async16(vst + (uint32_t)(row * AVP + c4) * 4u,
                           vb + (size_t)(kg + row) * DIM + c4);
            }
            CP_COMMIT();
        }

        const float* Ks = sm + Q_FLOATS + (kt & 1) * KV_STAGE;
        const float* Vs = Ks + KV_AOFF_V;

        // S = Q @ K^T : warp computes 16 x 64, S in registers.
        float c[8][4];
#pragma unroll
        for (int nt = 0; nt < 8; ++nt)
#pragma unroll
            for (int q = 0; q < 4; ++q) c[nt][q] = 0.f;

        const uint32_t* Qu = (const uint32_t*)Qs;
        const uint32_t* Ku = (const uint32_t*)Ks;
#pragma unroll
        for (int kk = 0; kk < 8; ++kk) {
            uint32_t a0 = Qu[r0 * AQP + kk * 8 + tig];
            uint32_t a1 = Qu[(r0 + 8) * AQP + kk * 8 + tig];
            uint32_t a2 = Qu[r0 * AQP + kk * 8 + tig + 4];
            uint32_t a3 = Qu[(r0 + 8) * AQP + kk * 8 + tig + 4];
#pragma unroll
            for (int nt = 0; nt < 8; ++nt) {
                uint32_t b0 = Ku[(nt * 8 + g) * AQP + kk * 8 + tig];
                uint32_t b1 = Ku[(nt * 8 + g) * AQP + kk * 8 + tig + 4];
                mma_tf32(c[nt], a0, a1, a2, a3, b0, b1);
            }
        }

        // Mask (from packed bits) + row max.  Scores are in log2 units.
        float mx0 = -1e30f, mx1 = -1e30f;
#pragma unroll
        for (int nt = 0; nt < 8; ++nt) {
            uint32_t nib = mbits >> (nt * 4);
            c[nt][0] = (nib & 1u) ? c[nt][0] : -1e30f;
            c[nt][1] = (nib & 2u) ? c[nt][1] : -1e30f;
            c[nt][2] = (nib & 4u) ? c[nt][2] : -1e30f;
            c[nt][3] = (nib & 8u) ? c[nt][3] : -1e30f;
            mx0 = fmaxf(mx0, fmaxf(c[nt][0], c[nt][1]));
            mx1 = fmaxf(mx1, fmaxf(c[nt][2], c[nt][3]));
        }
        mx0 = fmaxf(mx0, __shfl_xor_sync(0xffffffffu, mx0, 1));
        mx0 = fmaxf(mx0, __shfl_xor_sync(0xffffffffu, mx0, 2));
        mx1 = fmaxf(mx1, __shfl_xor_sync(0xffffffffu, mx1, 1));
        mx1 = fmaxf(mx1, __shfl_xor_sync(0xffffffffu, mx1, 2));

        float mn0 = fmaxf(m0, mx0), mn1 = fmaxf(m1, mx1);
        float al0 = exp2f(m0 - mn0), al1 = exp2f(m1 - mn1);
        float s0 = 0.f, s1 = 0.f;
#pragma unroll
        for (int nt = 0; nt < 8; ++nt) {
            float p0 = exp2f(c[nt][0] - mn0);
            float p1 = exp2f(c[nt][1] - mn0);
            float p2 = exp2f(c[nt][2] - mn1);
            float p3 = exp2f(c[nt][3] - mn1);
            s0 += p0 + p1;
            s1 += p2 + p3;
            c[nt][0] = to_tf32(p0); c[nt][1] = to_tf32(p1);
            c[nt][2] = to_tf32(p2); c[nt][3] = to_tf32(p3);
        }
        s0 += __shfl_xor_sync(0xffffffffu, s0, 1);
        s0 += __shfl_xor_sync(0xffffffffu, s0, 2);
        s1 += __shfl_xor_sync(0xffffffffu, s1, 1);
        s1 += __shfl_xor_sync(0xffffffffu, s1, 2);
        l0 = l0 * al0 + s0;
        l1 = l1 * al1 + s1;
        m0 = mn0; m1 = mn1;

#pragma unroll
        for (int nt = 0; nt < 8; ++nt) {
            o[nt][0] *= al0; o[nt][1] *= al0;
            o[nt][2] *= al1; o[nt][3] *= al1;
        }

        // O += P @ V.  P A-fragments from c[kk] via quad shuffles:
        // C-frag cols {2t,2t+1} -> A-frag cols {t, t+4}.
        const uint32_t* Vu = (const uint32_t*)Vs;
        const int base = lane & ~3;
        const int sl0 = base + (tig >> 1);
        const int sl1 = sl0 + 2;
        const bool oddt = (tig & 1);
#pragma unroll
        for (int kk = 0; kk < 8; ++kk) {
            float x00 = __shfl_sync(0xffffffffu, c[kk][0], sl0);
            float x01 = __shfl_sync(0xffffffffu, c[kk][1], sl0);
            float x10 = __shfl_sync(0xffffffffu, c[kk][0], sl1);
            float x11 = __shfl_sync(0xffffffffu, c[kk][1], sl1);
            float y00 = __shfl_sync(0xffffffffu, c[kk][2], sl0);
            float y01 = __shfl_sync(0xffffffffu, c[kk][3], sl0);
            float y10 = __shfl_sync(0xffffffffu, c[kk][2], sl1);
            float y11 = __shfl_sync(0xffffffffu, c[kk][3], sl1);
            uint32_t a0 = __float_as_uint(oddt ? x01 : x00);
            uint32_t a1 = __float_as_uint(oddt ? y01 : y00);
            uint32_t a2 = __float_as_uint(oddt ? x11 : x10);
            uint32_t a3 = __float_as_uint(oddt ? y11 : y10);
#pragma unroll
            for (int nt = 0; nt < 8; ++nt) {
                uint32_t b0 = Vu[(kk * 8 + tig) * AVP + nt * 8 + g];
                uint32_t b1 = Vu[(kk * 8 + tig + 4) * AVP + nt * 8 + g];
                mma_tf32(o[nt], a0, a1, a2, a3, b0, b1);
            }
        }
    }

    // Final normalize + store (merged-head layout, tf32-rounded for o-proj).
    float inv0 = 1.f / l0, inv1 = 1.f / l1;
    float* od = ctx + ((size_t)b * SEQ + q0 + r0) * DIM + h * HDIM;
#pragma unroll
    for (int nt = 0; nt < 8; ++nt) {
        *(float2*)(od + nt * 8 + 2 * tig) =
            make_float2(to_tf32(o[nt][0] * inv0), to_tf32(o[nt][1] * inv0));
        *(float2*)(od + (size_t)8 * DIM + nt * 8 + 2 * tig) =
            make_float2(to_tf32(o[nt][2] * inv1), to_tf32(o[nt][3] * inv1));
    }
}

// ---------------------------------------------------------------------------
// Launch
// ---------------------------------------------------------------------------
extern "C" void kernel_launch(void* const* d_in, const int* in_sizes, int n_in,
                              void* d_out, int out_size)
{
    (void)in_sizes; (void)n_in; (void)out_size;
    const float* Q  = (const float*)d_in[0];
    const float* K  = (const float*)d_in[1];
    const float* V  = (const float*)d_in[2];
    const int* mask = (const int*)d_in[3];
    const float* Wq = (const float*)d_in[4];
    const float* bq = (const float*)d_in[5];
    const float* Wk = (const float*)d_in[6];
    const float* bk = (const float*)d_in[7];
    const float* Wv = (const float*)d_in[8];
    const float* bv = (const float*)d_in[9];
    const float* Wo = (const float*)d_in[10];
    const float* bo = (const float*)d_in[11];
    float* out = (float*)d_out;

    float* cp;
    cudaGetSymbolAddress((void**)&cp, g_ctx);

    cudaFuncSetAttribute(qkv_gemm_kernel,
                         cudaFuncAttributeMaxDynamicSharedMemorySize,
                         GEMM_SMEM_BYTES);
    cudaFuncSetAttribute(oproj_gemm_kernel,
                         cudaFuncAttributeMaxDynamicSharedMemorySize,
                         GEMM_SMEM_BYTES);
    cudaFuncSetAttribute(attn_mma_kernel,
                         cudaFuncAttributeMaxDynamicSharedMemorySize,
                         ATTN_SMEM_BYTES);

    // Pre-round all four weight matrices to tf32.
    dim3 rwgrid(DIM * DIM / (256 * 4), 4);
    round_w_kernel<<<rwgrid, 256>>>(Wq, Wk, Wv, Wo);

    // Batched QKV projections (one launch, grid.z = 3).
    dim3 qkvgrid(DIM / 128, MROWS / 128, 3);
    qkv_gemm_kernel<<<qkvgrid, 256, GEMM_SMEM_BYTES>>>(Q, K, V, bq, bk, bv);

    // Attention.
    dim3 agrid(SEQ / 128, NHEAD, BSZ);  // (16, 16, 2)
    attn_mma_kernel<<<agrid, 256, ATTN_SMEM_BYTES>>>(mask, cp);

    // Output projection.
    dim3 ggrid(DIM / 128, MROWS / 128);
    oproj_gemm_kernel<<<ggrid, 256, GEMM_SMEM_BYTES>>>(bo, out);
}

// round 8
// speedup vs baseline: 1.6103x; 1.6103x over previous
#include <cuda_runtime.h>
#include <cuda_fp16.h>
#include <cstdint>

#define BSZ 2
#define SEQ 2048
#define DIM 1024
#define NHEAD 16
#define HDIM 64
#define MROWS (BSZ * SEQ)   // 4096

// Scratch (allocation-free requirement -> __device__ globals), all fp16.
__device__ __half g_hin[(size_t)3 * MROWS * DIM];  // converted inputs Q,K,V
__device__ __half g_hwt[(size_t)4 * DIM * DIM];    // W^T fp16 (Wq pre-scaled)
__device__ __half g_hq[(size_t)MROWS * DIM];       // q proj (scaled)
__device__ __half g_hk[(size_t)MROWS * DIM];       // k proj
__device__ __half g_vt[(size_t)BSZ * DIM * SEQ];   // v proj, transposed [b][dim][s]
__device__ __half g_hctx[(size_t)MROWS * DIM];     // attention output

// 0.125 (1/sqrt(64)) * log2(e): folded into Wq/bq so softmax can use exp2.
#define QSCALE 0.1803368801111137f

__device__ __forceinline__ uint32_t smem_u32(const void* p) {
    uint32_t a;
    asm("{ .reg .u64 t; cvta.to.shared.u64 t, %1; cvt.u32.u64 %0, t; }"
        : "=r"(a) : "l"(p));
    return a;
}

__device__ __forceinline__ void cp_async16(uint32_t dst, const void* src) {
    asm volatile("cp.async.cg.shared.global [%0], [%1], 16;"
                 :: "r"(dst), "l"(src));
}
#define CP_COMMIT() asm volatile("cp.async.commit_group;" ::: "memory")
#define CP_WAIT0()  asm volatile("cp.async.wait_group 0;" ::: "memory")
#define CP_WAIT1()  asm volatile("cp.async.wait_group 1;" ::: "memory")

__device__ __forceinline__ uint32_t pack_h2(float lo, float hi) {
    __half2 h = __floats2half2_rn(lo, hi);
    return *(uint32_t*)&h;
}

// m16n8k16 fp16 HMMA, fp32 accumulate.
__device__ __forceinline__ void mma_f16(float c[4],
                                        uint32_t a0, uint32_t a1,
                                        uint32_t a2, uint32_t a3,
                                        uint32_t b0, uint32_t b1) {
    asm volatile(
        "mma.sync.aligned.m16n8k16.row.col.f32.f16.f16.f32 "
        "{%0,%1,%2,%3}, {%4,%5,%6,%7}, {%8,%9}, {%0,%1,%2,%3};"
        : "+f"(c[0]), "+f"(c[1]), "+f"(c[2]), "+f"(c[3])
        : "r"(a0), "r"(a1), "r"(a2), "r"(a3), "r"(b0), "r"(b1));
}

// ---------------------------------------------------------------------------
// Input convert: fp32 -> fp16, Q/K/V in one launch (grid.y = 3).
// ---------------------------------------------------------------------------
__global__ __launch_bounds__(256) void convert_in_kernel(
    const float* __restrict__ Q, const float* __restrict__ K,
    const float* __restrict__ V)
{
    const int z = blockIdx.y;
    const float* src = (z == 0) ? Q : (z == 1) ? K : V;
    size_t off = ((size_t)blockIdx.x * 256 + threadIdx.x) * 8;
    float4 v0 = *(const float4*)(src + off);
    float4 v1 = *(const float4*)(src + off + 4);
    __half2* dst = (__half2*)(g_hin + (size_t)z * MROWS * DIM + off);
    uint4 pk;
    pk.x = pack_h2(v0.x, v0.y);
    pk.y = pack_h2(v0.z, v0.w);
    pk.z = pack_h2(v1.x, v1.y);
    pk.w = pack_h2(v1.z, v1.w);
    *(uint4*)dst = pk;
}

// ---------------------------------------------------------------------------
// Weight transpose+convert: g_hwt[z][n][k] = fp16(W[z][k][n] * scale).
// ---------------------------------------------------------------------------
__global__ __launch_bounds__(256) void convert_wt_kernel(
    const float* __restrict__ Wq, const float* __restrict__ Wk,
    const float* __restrict__ Wv, const float* __restrict__ Wo)
{
    __shared__ float t[32][33];
    const int z = blockIdx.z;
    const float* W = (z == 0) ? Wq : (z == 1) ? Wk : (z == 2) ? Wv : Wo;
    const float scale = (z == 0) ? QSCALE : 1.0f;
    __half* WT = g_hwt + (size_t)z * DIM * DIM;
    const int bx = blockIdx.x * 32;   // n
    const int by = blockIdx.y * 32;   // k
    const int x = threadIdx.x, y = threadIdx.y;
#pragma unroll
    for (int j = 0; j < 32; j += 8)
        t[y + j][x] = W[(size_t)(by + y + j) * DIM + bx + x];
    __syncthreads();
#pragma unroll
    for (int j = 0; j < 32; j += 8)
        WT[(size_t)(bx + y + j) * DIM + by + x] =
            __float2half(t[x][y + j] * scale);
}

// ---------------------------------------------------------------------------
// fp16 GEMM: acc[4096,1024] = A @ WT^T (WT is [n][k]), + bias*bscale.
// 128x128 tile, BK=32 (2 k16 steps), cp.async 3-stage, one barrier/chunk.
// MODE 0: half row-major out.  MODE 1: half transposed out ([b][dim][s]).
// MODE 2: float row-major out.
// ---------------------------------------------------------------------------
#define PAH 40                               // halves pitch (A and WT stages)
#define SB_OFF (128 * PAH * 2)               // 10240 B: B within stage
#define STAGE_BYTES (2 * 128 * PAH * 2)      // 20480 B
#define OFF_BIAS_B (3 * STAGE_BYTES)         // 61440
#define GEMM_SMEM_BYTES (OFF_BIAS_B + 128 * 4)

__device__ __forceinline__ void gemm_issue_h(
    uint32_t sbase, int s, int ch, const __half* __restrict__ A,
    const __half* __restrict__ WT, int m0, int n0, int tid)
{
    uint32_t sa = sbase + (uint32_t)(s * STAGE_BYTES);
    uint32_t sb = sa + SB_OFF;
    const __half* Ap = A + (size_t)m0 * DIM + ch * 32;
    const __half* Wp = WT + (size_t)n0 * DIM + ch * 32;
#pragma unroll
    for (int u = 0; u < 2; ++u) {
        int i = tid + u * 256;               // 512: 128 rows x 4 chunks
        int row = i >> 2, c16 = i & 3;
        cp_async16(sa + (uint32_t)(row * 80 + c16 * 16),
                   Ap + (size_t)row * DIM + c16 * 8);
        cp_async16(sb + (uint32_t)(row * 80 + c16 * 16),
                   Wp + (size_t)row * DIM + c16 * 8);
    }
}

template <int MODE>
__device__ __forceinline__ void gemm_body_h(
    const __half* __restrict__ A, const __half* __restrict__ WT,
    const float* __restrict__ bias, void* Cout, float bscale, char* smc)
{
    float* sbias = (float*)(smc + OFF_BIAS_B);
    const uint32_t sbase = smem_u32(smc);
    const int tid = threadIdx.x;
    const int wid = tid >> 5, lane = tid & 31;
    const int wm = wid >> 2, wn = wid & 3;
    const int g = lane >> 2, tig = lane & 3;
    const int n0 = blockIdx.x * 128;
    const int m0 = blockIdx.y * 128;

    if (tid < 128) sbias[tid] = bias[n0 + tid] * bscale;

    float c[4][4][4];
#pragma unroll
    for (int mt = 0; mt < 4; ++mt)
#pragma unroll
        for (int nt = 0; nt < 4; ++nt)
#pragma unroll
            for (int q = 0; q < 4; ++q) c[mt][nt][q] = 0.f;

    gemm_issue_h(sbase, 0, 0, A, WT, m0, n0, tid);
    CP_COMMIT();
    gemm_issue_h(sbase, 1, 1, A, WT, m0, n0, tid);
    CP_COMMIT();

    for (int ch = 0; ch < 32; ++ch) {
        if (ch == 31) CP_WAIT0(); else CP_WAIT1();
        __syncthreads();
        if (ch < 30) {
            gemm_issue_h(sbase, (ch + 2) % 3, ch + 2, A, WT, m0, n0, tid);
            CP_COMMIT();
        }

        const uint32_t* sA = (const uint32_t*)(smc + (ch % 3) * STAGE_BYTES);
        const uint32_t* sB = (const uint32_t*)(smc + (ch % 3) * STAGE_BYTES
                                               + SB_OFF);

#pragma unroll
        for (int kk = 0; kk < 2; ++kk) {
            uint32_t af[4][4], bf[4][2];
#pragma unroll
            for (int mt = 0; mt < 4; ++mt) {
                int r0 = wm * 64 + mt * 16 + g;
                af[mt][0] = sA[r0 * 20 + kk * 8 + tig];
                af[mt][1] = sA[(r0 + 8) * 20 + kk * 8 + tig];
                af[mt][2] = sA[r0 * 20 + kk * 8 + tig + 4];
                af[mt][3] = sA[(r0 + 8) * 20 + kk * 8 + tig + 4];
            }
#pragma unroll
            for (int nt = 0; nt < 4; ++nt) {
                int cb = wn * 32 + nt * 8 + g;
                bf[nt][0] = sB[cb * 20 + kk * 8 + tig];
                bf[nt][1] = sB[cb * 20 + kk * 8 + tig + 4];
            }
#pragma unroll
            for (int mt = 0; mt < 4; ++mt)
#pragma unroll
                for (int nt = 0; nt < 4; ++nt)
                    mma_f16(c[mt][nt], af[mt][0], af[mt][1], af[mt][2],
                            af[mt][3], bf[nt][0], bf[nt][1]);
        }
    }

#pragma unroll
    for (int mt = 0; mt < 4; ++mt) {
        int row = m0 + wm * 64 + mt * 16 + g;
#pragma unroll
        for (int nt = 0; nt < 4; ++nt) {
            int col = n0 + wn * 32 + nt * 8 + 2 * tig;
            float b0 = sbias[col - n0], b1 = sbias[col - n0 + 1];
            float v00 = c[mt][nt][0] + b0, v01 = c[mt][nt][1] + b1;
            float v10 = c[mt][nt][2] + b0, v11 = c[mt][nt][3] + b1;
            if (MODE == 0) {
                __half* C = (__half*)Cout;
                *(uint32_t*)(C + (size_t)row * DIM + col) = pack_h2(v00, v01);
                *(uint32_t*)(C + (size_t)(row + 8) * DIM + col) =
                    pack_h2(v10, v11);
            } else if (MODE == 1) {
                __half* VT = (__half*)Cout;   // [b][dim][s]
                int bb = row >> 11, ss = row & 2047;
                VT[((size_t)bb * DIM + col) * SEQ + ss] = __float2half(v00);
                VT[((size_t)bb * DIM + col + 1) * SEQ + ss] = __float2half(v01);
                VT[((size_t)bb * DIM + col) * SEQ + ss + 8] = __float2half(v10);
                VT[((size_t)bb * DIM + col + 1) * SEQ + ss + 8] =
                    __float2half(v11);
            } else {
                float* C = (float*)Cout;
                *(float2*)(C + (size_t)row * DIM + col) = make_float2(v00, v01);
                *(float2*)(C + (size_t)(row + 8) * DIM + col) =
                    make_float2(v10, v11);
            }
        }
    }
}

// Batched QKV projection (grid.z = 3). q gets QSCALE (folded into Wq/bq);
// v is written transposed for the PV B-fragment layout.
__global__ __launch_bounds__(256, 2) void qkv_gemm_kernel(
    const float* __restrict__ bq, const float* __restrict__ bk,
    const float* __restrict__ bv)
{
    extern __shared__ char smc[];
    const int z = blockIdx.z;
    const __half* A = g_hin + (size_t)z * MROWS * DIM;
    const __half* WT = g_hwt + (size_t)z * DIM * DIM;
    if (z == 0)
        gemm_body_h<0>(A, WT, bq, g_hq, QSCALE, smc);
    else if (z == 1)
        gemm_body_h<0>(A, WT, bk, g_hk, 1.0f, smc);
    else
        gemm_body_h<1>(A, WT, bv, g_vt, 1.0f, smc);
}

__global__ __launch_bounds__(256, 2) void oproj_gemm_kernel(
    const float* __restrict__ bias, float* __restrict__ C)
{
    extern __shared__ char smc[];
    gemm_body_h<2>(g_hctx, g_hwt + (size_t)3 * DIM * DIM, bias, C, 1.0f, smc);
}

// ---------------------------------------------------------------------------
// FA2 attention, fp16 MMAs: block = 128 q rows x one head x one batch.
// Warp owns 16 q rows x 64 keys/tile. P C-frags ARE the next A-frags (k16):
// no shuffles, no SMEM round-trip. V pre-transposed in gmem.
// ---------------------------------------------------------------------------
#define APH 72                                // halves pitch
#define Q_BYTES (128 * APH * 2)               // 18432
#define KV_V_OFF (64 * APH * 2)               // 9216
#define KV_STAGE_B (2 * 64 * APH * 2)         // 18432
#define ATTN_SMEM_BYTES (Q_BYTES + 2 * KV_STAGE_B)   // 55296

__global__ __launch_bounds__(256, 2) void attn_mma_kernel(
    const int* __restrict__ mask)
{
    extern __shared__ char smc[];
    const uint32_t sbase = smem_u32(smc);

    const int tid = threadIdx.x;
    const int wid = tid >> 5, lane = tid & 31;
    const int g = lane >> 2, tig = lane & 3;
    const int q0 = blockIdx.x * 128;
    const int h = blockIdx.y;
    const int b = blockIdx.z;

    const __half* qb = g_hq + ((size_t)b * SEQ + q0) * DIM + h * HDIM;
    const __half* kb = g_hk + (size_t)b * SEQ * DIM + h * HDIM;
    const __half* vtb = g_vt + ((size_t)b * DIM + h * HDIM) * SEQ;

    // Prologue: stage Q (128x64) + K/V tile 0.
#pragma unroll
    for (int u = 0; u < 4; ++u) {
        int i = tid + u * 256;               // 1024: 128 rows x 8 chunks
        int row = i >> 3, c16 = i & 7;
        cp_async16(sbase + (uint32_t)(row * 144 + c16 * 16),
                   qb + (size_t)row * DIM + c16 * 8);
    }
    {
        uint32_t kst = sbase + Q_BYTES;
        uint32_t vst = kst + KV_V_OFF;
#pragma unroll
        for (int u = 0; u < 2; ++u) {
            int i = tid + u * 256;           // 512: 64 rows x 8 chunks
            int row = i >> 3, c16 = i & 7;
            cp_async16(kst + (uint32_t)(row * 144 + c16 * 16),
                       kb + (size_t)row * DIM + c16 * 8);
            cp_async16(vst + (uint32_t)(row * 144 + c16 * 16),
                       vtb + (size_t)row * SEQ + c16 * 8);
        }
    }
    CP_COMMIT();

    const int r0 = wid * 16 + g;
    float m0 = -1e30f, m1 = -1e30f, l0 = 0.f, l1 = 0.f;
    float o[8][4];
#pragma unroll
    for (int nt = 0; nt < 8; ++nt)
#pragma unroll
        for (int q = 0; q < 4; ++q) o[nt][q] = 0.f;

    const int* mbase0 = mask + (size_t)(q0 + r0) * SEQ + 2 * tig;
    const int* mbase1 = mbase0 + 8 * SEQ;

    for (int kt = 0; kt < SEQ / 64; ++kt) {
        const int kg0 = kt * 64;
        CP_WAIT0();
        __syncthreads();

        // Prefetch next K/V tile.
        if (kt < SEQ / 64 - 1) {
            int s = (kt + 1) & 1;
            int kg = (kt + 1) * 64;
            uint32_t kst = sbase + Q_BYTES + (uint32_t)(s * KV_STAGE_B);
            uint32_t vst = kst + KV_V_OFF;
#pragma unroll
            for (int u = 0; u < 2; ++u) {
                int i = tid + u * 256;
                int row = i >> 3, c16 = i & 7;
                cp_async16(kst + (uint32_t)(row * 144 + c16 * 16),
                           kb + (size_t)(kg + row) * DIM + c16 * 8);
                cp_async16(vst + (uint32_t)(row * 144 + c16 * 16),
                           vtb + (size_t)row * SEQ + kg + c16 * 8);
            }
            CP_COMMIT();
        }

        const uint32_t* Qu = (const uint32_t*)smc;
        const uint32_t* Ku = (const uint32_t*)(smc + Q_BYTES
                                               + (kt & 1) * KV_STAGE_B);
        const uint32_t* Vu = Ku + KV_V_OFF / 4;

        // S = Q @ K^T : 4 k16 steps, 8 n-tiles, S in registers.
        float c[8][4];
#pragma unroll
        for (int nt = 0; nt < 8; ++nt)
#pragma unroll
            for (int q = 0; q < 4; ++q) c[nt][q] = 0.f;

#pragma unroll
        for (int kk = 0; kk < 4; ++kk) {
            uint32_t a0 = Qu[r0 * 36 + kk * 8 + tig];
            uint32_t a1 = Qu[(r0 + 8) * 36 + kk * 8 + tig];
            uint32_t a2 = Qu[r0 * 36 + kk * 8 + tig + 4];
            uint32_t a3 = Qu[(r0 + 8) * 36 + kk * 8 + tig + 4];
#pragma unroll
            for (int nt = 0; nt < 8; ++nt) {
                uint32_t b0 = Ku[(nt * 8 + g) * 36 + kk * 8 + tig];
                uint32_t b1 = Ku[(nt * 8 + g) * 36 + kk * 8 + tig + 4];
                mma_f16(c[nt], a0, a1, a2, a3, b0, b1);
            }
        }

        // Mask + row max (scores in log2 units).
        float mx0 = -1e30f, mx1 = -1e30f;
#pragma unroll
        for (int nt = 0; nt < 8; ++nt) {
            int2 ma = *(const int2*)(mbase0 + kg0 + nt * 8);
            int2 mb = *(const int2*)(mbase1 + kg0 + nt * 8);
            c[nt][0] = ma.x ? c[nt][0] : -1e30f;
            c[nt][1] = ma.y ? c[nt][1] : -1e30f;
            c[nt][2] = mb.x ? c[nt][2] : -1e30f;
            c[nt][3] = mb.y ? c[nt][3] : -1e30f;
            mx0 = fmaxf(mx0, fmaxf(c[nt][0], c[nt][1]));
            mx1 = fmaxf(mx1, fmaxf(c[nt][2], c[nt][3]));
        }
        mx0 = fmaxf(mx0, __shfl_xor_sync(0xffffffffu, mx0, 1));
        mx0 = fmaxf(mx0, __shfl_xor_sync(0xffffffffu, mx0, 2));
        mx1 = fmaxf(mx1, __shfl_xor_sync(0xffffffffu, mx1, 1));
        mx1 = fmaxf(mx1, __shfl_xor_sync(0xffffffffu, mx1, 2));

        float mn0 = fmaxf(m0, mx0), mn1 = fmaxf(m1, mx1);
        float al0 = exp2f(m0 - mn0), al1 = exp2f(m1 - mn1);
        float s0 = 0.f, s1 = 0.f;
#pragma unroll
        for (int nt = 0; nt < 8; ++nt) {
            float p0 = exp2f(c[nt][0] - mn0);
            float p1 = exp2f(c[nt][1] - mn0);
            float p2 = exp2f(c[nt][2] - mn1);
            float p3 = exp2f(c[nt][3] - mn1);
            s0 += p0 + p1;
            s1 += p2 + p3;
            c[nt][0] = p0; c[nt][1] = p1; c[nt][2] = p2; c[nt][3] = p3;
        }
        s0 += __shfl_xor_sync(0xffffffffu, s0, 1);
        s0 += __shfl_xor_sync(0xffffffffu, s0, 2);
        s1 += __shfl_xor_sync(0xffffffffu, s1, 1);
        s1 += __shfl_xor_sync(0xffffffffu, s1, 2);
        l0 = l0 * al0 + s0;
        l1 = l1 * al1 + s1;
        m0 = mn0; m1 = mn1;

#pragma unroll
        for (int nt = 0; nt < 8; ++nt) {
            o[nt][0] *= al0; o[nt][1] *= al0;
            o[nt][2] *= al1; o[nt][3] *= al1;
        }

        // O += P @ V: A-frags come straight from the S C-frags (k16 magic).
#pragma unroll
        for (int kk = 0; kk < 4; ++kk) {
            uint32_t a0 = pack_h2(c[2 * kk][0], c[2 * kk][1]);
            uint32_t a1 = pack_h2(c[2 * kk][2], c[2 * kk][3]);
            uint32_t a2 = pack_h2(c[2 * kk + 1][0], c[2 * kk + 1][1]);
            uint32_t a3 = pack_h2(c[2 * kk + 1][2], c[2 * kk + 1][3]);
#pragma unroll
            for (int nt = 0; nt < 8; ++nt) {
                uint32_t b0 = Vu[(nt * 8 + g) * 36 + kk * 8 + tig];
                uint32_t b1 = Vu[(nt * 8 + g) * 36 + kk * 8 + tig + 4];
                mma_f16(o[nt], a0, a1, a2, a3, b0, b1);
            }
        }
    }

    // Final normalize + store fp16 (merged-head layout).
    float inv0 = 1.f / l0, inv1 = 1.f / l1;
    __half* od = g_hctx + ((size_t)b * SEQ + q0 + r0) * DIM + h * HDIM;
#pragma unroll
    for (int nt = 0; nt < 8; ++nt) {
        *(uint32_t*)(od + nt * 8 + 2 * tig) =
            pack_h2(o[nt][0] * inv0, o[nt][1] * inv0);
        *(uint32_t*)(od + (size_t)8 * DIM + nt * 8 + 2 * tig) =
            pack_h2(o[nt][2] * inv1, o[nt][3] * inv1);
    }
}

// ---------------------------------------------------------------------------
// Launch
// ---------------------------------------------------------------------------
extern "C" void kernel_launch(void* const* d_in, const int* in_sizes, int n_in,
                              void* d_out, int out_size)
{
    (void)in_sizes; (void)n_in; (void)out_size;
    const float* Q  = (const float*)d_in[0];
    const float* K  = (const float*)d_in[1];
    const float* V  = (const float*)d_in[2];
    const int* mask = (const int*)d_in[3];
    const float* Wq = (const float*)d_in[4];
    const float* bq = (const float*)d_in[5];
    const float* Wk = (const float*)d_in[6];
    const float* bk = (const float*)d_in[7];
    const float* Wv = (const float*)d_in[8];
    const float* bv = (const float*)d_in[9];
    const float* Wo = (const float*)d_in[10];
    const float* bo = (const float*)d_in[11];
    float* out = (float*)d_out;

    cudaFuncSetAttribute(qkv_gemm_kernel,
                         cudaFuncAttributeMaxDynamicSharedMemorySize,
                         GEMM_SMEM_BYTES);
    cudaFuncSetAttribute(oproj_gemm_kernel,
                         cudaFuncAttributeMaxDynamicSharedMemorySize,
                         GEMM_SMEM_BYTES);
    cudaFuncSetAttribute(attn_mma_kernel,
                         cudaFuncAttributeMaxDynamicSharedMemorySize,
                         ATTN_SMEM_BYTES);

    // Convert inputs and weights to fp16 (weights transposed, Wq pre-scaled).
    dim3 cigrid(MROWS * DIM / (256 * 8), 3);
    convert_in_kernel<<<cigrid, 256>>>(Q, K, V);
    dim3 cwgrid(32, 32, 4), cwblk(32, 8);
    convert_wt_kernel<<<cwgrid, cwblk>>>(Wq, Wk, Wv, Wo);

    // Batched QKV projections.
    dim3 qkvgrid(DIM / 128, MROWS / 128, 3);
    qkv_gemm_kernel<<<qkvgrid, 256, GEMM_SMEM_BYTES>>>(bq, bk, bv);

    // Attention.
    dim3 agrid(SEQ / 128, NHEAD, BSZ);  // (16, 16, 2)
    attn_mma_kernel<<<agrid, 256, ATTN_SMEM_BYTES>>>(mask);

    // Output projection.
    dim3 ggrid(DIM / 128, MROWS / 128);
    oproj_gemm_kernel<<<ggrid, 256, GEMM_SMEM_BYTES>>>(bo, out);
}

// round 9
// speedup vs baseline: 1.7999x; 1.1177x over previous
#include <cuda_runtime.h>
#include <cuda_fp16.h>
#include <cstdint>

#define BSZ 2
#define SEQ 2048
#define DIM 1024
#define NHEAD 16
#define HDIM 64
#define MROWS (BSZ * SEQ)   // 4096

// Scratch (allocation-free requirement -> __device__ globals), all fp16.
__device__ __half g_hin[(size_t)3 * MROWS * DIM];  // converted inputs Q,K,V
__device__ __half g_hwt[(size_t)4 * DIM * DIM];    // W^T fp16 (Wq pre-scaled)
__device__ __half g_hq[(size_t)MROWS * DIM];       // q proj (scaled)
__device__ __half g_hk[(size_t)MROWS * DIM];       // k proj
__device__ __half g_vt[(size_t)BSZ * DIM * SEQ];   // v proj, transposed [b][dim][s]
__device__ __half g_hctx[(size_t)MROWS * DIM];     // attention output

// 0.125 (1/sqrt(64)) * log2(e): folded into Wq/bq so softmax can use exp2.
#define QSCALE 0.1803368801111137f

__device__ __forceinline__ uint32_t smem_u32(const void* p) {
    uint32_t a;
    asm("{ .reg .u64 t; cvta.to.shared.u64 t, %1; cvt.u32.u64 %0, t; }"
        : "=r"(a) : "l"(p));
    return a;
}

__device__ __forceinline__ void cp_async16(uint32_t dst, const void* src) {
    asm volatile("cp.async.cg.shared.global [%0], [%1], 16;"
                 :: "r"(dst), "l"(src));
}
#define CP_COMMIT() asm volatile("cp.async.commit_group;" ::: "memory")
#define CP_WAIT0()  asm volatile("cp.async.wait_group 0;" ::: "memory")
#define CP_WAIT1()  asm volatile("cp.async.wait_group 1;" ::: "memory")

__device__ __forceinline__ uint32_t pack_h2(float lo, float hi) {
    __half2 h = __floats2half2_rn(lo, hi);
    return *(uint32_t*)&h;
}

// ldmatrix x4: loads four 8x8 b16 tiles; lanes 0-7/8-15/16-23/24-31 give the
// row addresses for matrices 0/1/2/3.
__device__ __forceinline__ void ldsm_x4(uint32_t& r0, uint32_t& r1,
                                        uint32_t& r2, uint32_t& r3,
                                        uint32_t addr) {
    asm volatile("ldmatrix.sync.aligned.m8n8.x4.shared.b16 "
                 "{%0,%1,%2,%3}, [%4];"
                 : "=r"(r0), "=r"(r1), "=r"(r2), "=r"(r3) : "r"(addr));
}

// m16n8k16 fp16 HMMA, fp32 accumulate.
__device__ __forceinline__ void mma_f16(float c[4],
                                        uint32_t a0, uint32_t a1,
                                        uint32_t a2, uint32_t a3,
                                        uint32_t b0, uint32_t b1) {
    asm volatile(
        "mma.sync.aligned.m16n8k16.row.col.f32.f16.f16.f32 "
        "{%0,%1,%2,%3}, {%4,%5,%6,%7}, {%8,%9}, {%0,%1,%2,%3};"
        : "+f"(c[0]), "+f"(c[1]), "+f"(c[2]), "+f"(c[3])
        : "r"(a0), "r"(a1), "r"(a2), "r"(a3), "r"(b0), "r"(b1));
}

// ---------------------------------------------------------------------------
// Input convert: fp32 -> fp16, Q/K/V in one launch (grid.y = 3).
// ---------------------------------------------------------------------------
__global__ __launch_bounds__(256) void convert_in_kernel(
    const float* __restrict__ Q, const float* __restrict__ K,
    const float* __restrict__ V)
{
    const int z = blockIdx.y;
    const float* src = (z == 0) ? Q : (z == 1) ? K : V;
    size_t off = ((size_t)blockIdx.x * 256 + threadIdx.x) * 8;
    float4 v0 = *(const float4*)(src + off);
    float4 v1 = *(const float4*)(src + off + 4);
    __half2* dst = (__half2*)(g_hin + (size_t)z * MROWS * DIM + off);
    uint4 pk;
    pk.x = pack_h2(v0.x, v0.y);
    pk.y = pack_h2(v0.z, v0.w);
    pk.z = pack_h2(v1.x, v1.y);
    pk.w = pack_h2(v1.z, v1.w);
    *(uint4*)dst = pk;
}

// ---------------------------------------------------------------------------
// Weight transpose+convert: g_hwt[z][n][k] = fp16(W[z][k][n] * scale).
// ---------------------------------------------------------------------------
__global__ __launch_bounds__(256) void convert_wt_kernel(
    const float* __restrict__ Wq, const float* __restrict__ Wk,
    const float* __restrict__ Wv, const float* __restrict__ Wo)
{
    __shared__ float t[32][33];
    const int z = blockIdx.z;
    const float* W = (z == 0) ? Wq : (z == 1) ? Wk : (z == 2) ? Wv : Wo;
    const float scale = (z == 0) ? QSCALE : 1.0f;
    __half* WT = g_hwt + (size_t)z * DIM * DIM;
    const int bx = blockIdx.x * 32;   // n
    const int by = blockIdx.y * 32;   // k
    const int x = threadIdx.x, y = threadIdx.y;
#pragma unroll
    for (int j = 0; j < 32; j += 8)
        t[y + j][x] = W[(size_t)(by + y + j) * DIM + bx + x];
    __syncthreads();
#pragma unroll
    for (int j = 0; j < 32; j += 8)
        WT[(size_t)(bx + y + j) * DIM + by + x] =
            __float2half(t[x][y + j] * scale);
}

// ---------------------------------------------------------------------------
// fp16 GEMM: acc[4096,1024] = A @ WT^T (WT is [n][k]), + bias*bscale.
// 128x128 tile, BK=32 (2 k16 steps), cp.async 3-stage, one barrier/chunk,
// ldmatrix fragment loads.
// MODE 0: half row-major out.  MODE 1: half transposed out ([b][dim][s]).
// MODE 2: float row-major out.
// ---------------------------------------------------------------------------
#define PAH 40                               // halves pitch => 80 B
#define SB_OFF (128 * PAH * 2)               // 10240 B: B within stage
#define STAGE_BYTES (2 * 128 * PAH * 2)      // 20480 B
#define OFF_BIAS_B (3 * STAGE_BYTES)         // 61440
#define GEMM_SMEM_BYTES (OFF_BIAS_B + 128 * 4)

__device__ __forceinline__ void gemm_issue_h(
    uint32_t sbase, int s, int ch, const __half* __restrict__ A,
    const __half* __restrict__ WT, int m0, int n0, int tid)
{
    uint32_t sa = sbase + (uint32_t)(s * STAGE_BYTES);
    uint32_t sb = sa + SB_OFF;
    const __half* Ap = A + (size_t)m0 * DIM + ch * 32;
    const __half* Wp = WT + (size_t)n0 * DIM + ch * 32;
#pragma unroll
    for (int u = 0; u < 2; ++u) {
        int i = tid + u * 256;               // 512: 128 rows x 4 chunks
        int row = i >> 2, c16 = i & 3;
        cp_async16(sa + (uint32_t)(row * 80 + c16 * 16),
                   Ap + (size_t)row * DIM + c16 * 8);
        cp_async16(sb + (uint32_t)(row * 80 + c16 * 16),
                   Wp + (size_t)row * DIM + c16 * 8);
    }
}

template <int MODE>
__device__ __forceinline__ void gemm_body_h(
    const __half* __restrict__ A, const __half* __restrict__ WT,
    const float* __restrict__ bias, void* Cout, float bscale, char* smc)
{
    float* sbias = (float*)(smc + OFF_BIAS_B);
    const uint32_t sbase = smem_u32(smc);
    const int tid = threadIdx.x;
    const int wid = tid >> 5, lane = tid & 31;
    const int wm = wid >> 2, wn = wid & 3;
    const int g = lane >> 2, tig = lane & 3;
    const int n0 = blockIdx.x * 128;
    const int m0 = blockIdx.y * 128;

    if (tid < 128) sbias[tid] = bias[n0 + tid] * bscale;

    // ldmatrix per-lane address offsets (A-style and B-style frags).
    const uint32_t afoff = (uint32_t)(
        (wm * 64 + ((lane >> 3) & 1) * 8 + (lane & 7)) * 80 +
        ((lane >> 4) & 1) * 16);
    const uint32_t bfoff = (uint32_t)(
        (wn * 32 + ((lane >> 4) & 1) * 8 + (lane & 7)) * 80 +
        ((lane >> 3) & 1) * 16);

    float c[4][4][4];
#pragma unroll
    for (int mt = 0; mt < 4; ++mt)
#pragma unroll
        for (int nt = 0; nt < 4; ++nt)
#pragma unroll
            for (int q = 0; q < 4; ++q) c[mt][nt][q] = 0.f;

    gemm_issue_h(sbase, 0, 0, A, WT, m0, n0, tid);
    CP_COMMIT();
    gemm_issue_h(sbase, 1, 1, A, WT, m0, n0, tid);
    CP_COMMIT();

    for (int ch = 0; ch < 32; ++ch) {
        if (ch == 31) CP_WAIT0(); else CP_WAIT1();
        __syncthreads();
        if (ch < 30) {
            gemm_issue_h(sbase, (ch + 2) % 3, ch + 2, A, WT, m0, n0, tid);
            CP_COMMIT();
        }

        const uint32_t sAb = sbase + (uint32_t)((ch % 3) * STAGE_BYTES);
        const uint32_t sBb = sAb + SB_OFF;

#pragma unroll
        for (int kk = 0; kk < 2; ++kk) {
            uint32_t af[4][4], bf[4][2];
#pragma unroll
            for (int mt = 0; mt < 4; ++mt)
                ldsm_x4(af[mt][0], af[mt][1], af[mt][2], af[mt][3],
                        sAb + afoff + mt * 1280 + kk * 32);
#pragma unroll
            for (int p = 0; p < 2; ++p)
                ldsm_x4(bf[2 * p][0], bf[2 * p][1],
                        bf[2 * p + 1][0], bf[2 * p + 1][1],
                        sBb + bfoff + p * 1280 + kk * 32);
#pragma unroll
            for (int mt = 0; mt < 4; ++mt)
#pragma unroll
                for (int nt = 0; nt < 4; ++nt)
                    mma_f16(c[mt][nt], af[mt][0], af[mt][1], af[mt][2],
                            af[mt][3], bf[nt][0], bf[nt][1]);
        }
    }

#pragma unroll
    for (int mt = 0; mt < 4; ++mt) {
        int row = m0 + wm * 64 + mt * 16 + g;
#pragma unroll
        for (int nt = 0; nt < 4; ++nt) {
            int col = n0 + wn * 32 + nt * 8 + 2 * tig;
            float b0 = sbias[col - n0], b1 = sbias[col - n0 + 1];
            float v00 = c[mt][nt][0] + b0, v01 = c[mt][nt][1] + b1;
            float v10 = c[mt][nt][2] + b0, v11 = c[mt][nt][3] + b1;
            if (MODE == 0) {
                __half* C = (__half*)Cout;
                *(uint32_t*)(C + (size_t)row * DIM + col) = pack_h2(v00, v01);
                *(uint32_t*)(C + (size_t)(row + 8) * DIM + col) =
                    pack_h2(v10, v11);
            } else if (MODE == 1) {
                __half* VT = (__half*)Cout;   // [b][dim][s]
                int bb = row >> 11, ss = row & 2047;
                VT[((size_t)bb * DIM + col) * SEQ + ss] = __float2half(v00);
                VT[((size_t)bb * DIM + col + 1) * SEQ + ss] = __float2half(v01);
                VT[((size_t)bb * DIM + col) * SEQ + ss + 8] = __float2half(v10);
                VT[((size_t)bb * DIM + col + 1) * SEQ + ss + 8] =
                    __float2half(v11);
            } else {
                float* C = (float*)Cout;
                *(float2*)(C + (size_t)row * DIM + col) = make_float2(v00, v01);
                *(float2*)(C + (size_t)(row + 8) * DIM + col) =
                    make_float2(v10, v11);
            }
        }
    }
}

// Batched QKV projection (grid.z = 3). q gets QSCALE (folded into Wq/bq);
// v is written transposed for the PV B-fragment layout.
__global__ __launch_bounds__(256, 2) void qkv_gemm_kernel(
    const float* __restrict__ bq, const float* __restrict__ bk,
    const float* __restrict__ bv)
{
    extern __shared__ char smc[];
    const int z = blockIdx.z;
    const __half* A = g_hin + (size_t)z * MROWS * DIM;
    const __half* WT = g_hwt + (size_t)z * DIM * DIM;
    if (z == 0)
        gemm_body_h<0>(A, WT, bq, g_hq, QSCALE, smc);
    else if (z == 1)
        gemm_body_h<0>(A, WT, bk, g_hk, 1.0f, smc);
    else
        gemm_body_h<1>(A, WT, bv, g_vt, 1.0f, smc);
}

__global__ __launch_bounds__(256, 2) void oproj_gemm_kernel(
    const float* __restrict__ bias, float* __restrict__ C)
{
    extern __shared__ char smc[];
    gemm_body_h<2>(g_hctx, g_hwt + (size_t)3 * DIM * DIM, bias, C, 1.0f, smc);
}

// ---------------------------------------------------------------------------
// FA2 attention, fp16 MMAs + ldmatrix: block = 128 q rows x one head x one
// batch. Warp owns 16 q rows x 64 keys/tile. P C-frags ARE the next A-frags.
// ---------------------------------------------------------------------------
#define APH 72                                // halves pitch => 144 B
#define Q_BYTES (128 * APH * 2)               // 18432
#define KV_V_OFF (64 * APH * 2)               // 9216
#define KV_STAGE_B (2 * 64 * APH * 2)         // 18432
#define ATTN_SMEM_BYTES (Q_BYTES + 2 * KV_STAGE_B)   // 55296

__global__ __launch_bounds__(256, 2) void attn_mma_kernel(
    const int* __restrict__ mask)
{
    extern __shared__ char smc[];
    const uint32_t sbase = smem_u32(smc);

    const int tid = threadIdx.x;
    const int wid = tid >> 5, lane = tid & 31;
    const int g = lane >> 2, tig = lane & 3;
    const int q0 = blockIdx.x * 128;
    const int h = blockIdx.y;
    const int b = blockIdx.z;

    const __half* qb = g_hq + ((size_t)b * SEQ + q0) * DIM + h * HDIM;
    const __half* kb = g_hk + (size_t)b * SEQ * DIM + h * HDIM;
    const __half* vtb = g_vt + ((size_t)b * DIM + h * HDIM) * SEQ;

    // ldmatrix per-lane address offsets.
    const uint32_t qoff = (uint32_t)(
        (wid * 16 + ((lane >> 3) & 1) * 8 + (lane & 7)) * 144 +
        ((lane >> 4) & 1) * 16);
    const uint32_t bfoff = (uint32_t)(
        (((lane >> 4) & 1) * 8 + (lane & 7)) * 144 +
        ((lane >> 3) & 1) * 16);

    // Prologue: stage Q (128x64) + K/V tile 0.
#pragma unroll
    for (int u = 0; u < 4; ++u) {
        int i = tid + u * 256;               // 1024: 128 rows x 8 chunks
        int row = i >> 3, c16 = i & 7;
        cp_async16(sbase + (uint32_t)(row * 144 + c16 * 16),
                   qb + (size_t)row * DIM + c16 * 8);
    }
    {
        uint32_t kst = sbase + Q_BYTES;
        uint32_t vst = kst + KV_V_OFF;
#pragma unroll
        for (int u = 0; u < 2; ++u) {
            int i = tid + u * 256;           // 512: 64 rows x 8 chunks
            int row = i >> 3, c16 = i & 7;
            cp_async16(kst + (uint32_t)(row * 144 + c16 * 16),
                       kb + (size_t)row * DIM + c16 * 8);
            cp_async16(vst + (uint32_t)(row * 144 + c16 * 16),
                       vtb + (size_t)row * SEQ + c16 * 8);
        }
    }
    CP_COMMIT();

    const int r0 = wid * 16 + g;
    float m0 = -1e30f, m1 = -1e30f, l0 = 0.f, l1 = 0.f;
    float o[8][4];
#pragma unroll
    for (int nt = 0; nt < 8; ++nt)
#pragma unroll
        for (int q = 0; q < 4; ++q) o[nt][q] = 0.f;

    const int* mbase0 = mask + (size_t)(q0 + r0) * SEQ + 2 * tig;
    const int* mbase1 = mbase0 + 8 * SEQ;

    for (int kt = 0; kt < SEQ / 64; ++kt) {
        const int kg0 = kt * 64;
        CP_WAIT0();
        __syncthreads();

        // Prefetch next K/V tile.
        if (kt < SEQ / 64 - 1) {
            int s = (kt + 1) & 1;
            int kg = (kt + 1) * 64;
            uint32_t kst = sbase + Q_BYTES + (uint32_t)(s * KV_STAGE_B);
            uint32_t vst = kst + KV_V_OFF;
#pragma unroll
            for (int u = 0; u < 2; ++u) {
                int i = tid + u * 256;
                int row = i >> 3, c16 = i & 7;
                cp_async16(kst + (uint32_t)(row * 144 + c16 * 16),
                           kb + (size_t)(kg + row) * DIM + c16 * 8);
                cp_async16(vst + (uint32_t)(row * 144 + c16 * 16),
                           vtb + (size_t)row * SEQ + kg + c16 * 8);
            }
            CP_COMMIT();
        }

        const uint32_t kbase_s = sbase + Q_BYTES
                                 + (uint32_t)((kt & 1) * KV_STAGE_B);
        const uint32_t vbase_s = kbase_s + KV_V_OFF;

        // S = Q @ K^T : 4 k16 steps, 8 n-tiles, S in registers.
        float c[8][4];
#pragma unroll
        for (int nt = 0; nt < 8; ++nt)
#pragma unroll
            for (int q = 0; q < 4; ++q) c[nt][q] = 0.f;

#pragma unroll
        for (int kk = 0; kk < 4; ++kk) {
            uint32_t a0, a1, a2, a3;
            ldsm_x4(a0, a1, a2, a3, sbase + qoff + kk * 32);
#pragma unroll
            for (int p = 0; p < 4; ++p) {
                uint32_t b0, b1, b2, b3;
                ldsm_x4(b0, b1, b2, b3,
                        kbase_s + bfoff + p * 2304 + kk * 32);
                mma_f16(c[2 * p], a0, a1, a2, a3, b0, b1);
                mma_f16(c[2 * p + 1], a0, a1, a2, a3, b2, b3);
            }
        }

        // Mask + row max (scores in log2 units).
        float mx0 = -1e30f, mx1 = -1e30f;
#pragma unroll
        for (int nt = 0; nt < 8; ++nt) {
            int2 ma = *(const int2*)(mbase0 + kg0 + nt * 8);
            int2 mb = *(const int2*)(mbase1 + kg0 + nt * 8);
            c[nt][0] = ma.x ? c[nt][0] : -1e30f;
            c[nt][1] = ma.y ? c[nt][1] : -1e30f;
            c[nt][2] = mb.x ? c[nt][2] : -1e30f;
            c[nt][3] = mb.y ? c[nt][3] : -1e30f;
            mx0 = fmaxf(mx0, fmaxf(c[nt][0], c[nt][1]));
            mx1 = fmaxf(mx1, fmaxf(c[nt][2], c[nt][3]));
        }
        mx0 = fmaxf(mx0, __shfl_xor_sync(0xffffffffu, mx0, 1));
        mx0 = fmaxf(mx0, __shfl_xor_sync(0xffffffffu, mx0, 2));
        mx1 = fmaxf(mx1, __shfl_xor_sync(0xffffffffu, mx1, 1));
        mx1 = fmaxf(mx1, __shfl_xor_sync(0xffffffffu, mx1, 2));

        float mn0 = fmaxf(m0, mx0), mn1 = fmaxf(m1, mx1);
        float al0 = exp2f(m0 - mn0), al1 = exp2f(m1 - mn1);
        float s0 = 0.f, s1 = 0.f;
#pragma unroll
        for (int nt = 0; nt < 8; ++nt) {
            float p0 = exp2f(c[nt][0] - mn0);
            float p1 = exp2f(c[nt][1] - mn0);
            float p2 = exp2f(c[nt][2] - mn1);
            float p3 = exp2f(c[nt][3] - mn1);
            s0 += p0 + p1;
            s1 += p2 + p3;
            c[nt][0] = p0; c[nt][1] = p1; c[nt][2] = p2; c[nt][3] = p3;
        }
        s0 += __shfl_xor_sync(0xffffffffu, s0, 1);
        s0 += __shfl_xor_sync(0xffffffffu, s0, 2);
        s1 += __shfl_xor_sync(0xffffffffu, s1, 1);
        s1 += __shfl_xor_sync(0xffffffffu, s1, 2);
        l0 = l0 * al0 + s0;
        l1 = l1 * al1 + s1;
        m0 = mn0; m1 = mn1;

#pragma unroll
        for (int nt = 0; nt < 8; ++nt) {
            o[nt][0] *= al0; o[nt][1] *= al0;
            o[nt][2] *= al1; o[nt][3] *= al1;
        }

        // O += P @ V: A-frags come straight from the S C-frags (k16).
#pragma unroll
        for (int kk = 0; kk < 4; ++kk) {
            uint32_t a0 = pack_h2(c[2 * kk][0], c[2 * kk][1]);
            uint32_t a1 = pack_h2(c[2 * kk][2], c[2 * kk][3]);
            uint32_t a2 = pack_h2(c[2 * kk + 1][0], c[2 * kk + 1][1]);
            uint32_t a3 = pack_h2(c[2 * kk + 1][2], c[2 * kk + 1][3]);
#pragma unroll
            for (int p = 0; p < 4; ++p) {
                uint32_t b0, b1, b2, b3;
                ldsm_x4(b0, b1, b2, b3,
                        vbase_s + bfoff + p * 2304 + kk * 32);
                mma_f16(o[2 * p], a0, a1, a2, a3, b0, b1);
                mma_f16(o[2 * p + 1], a0, a1, a2, a3, b2, b3);
            }
        }
    }

    // Final normalize + store fp16 (merged-head layout).
    float inv0 = 1.f / l0, inv1 = 1.f / l1;
    __half* od = g_hctx + ((size_t)b * SEQ + q0 + r0) * DIM + h * HDIM;
#pragma unroll
    for (int nt = 0; nt < 8; ++nt) {
        *(uint32_t*)(od + nt * 8 + 2 * tig) =
            pack_h2(o[nt][0] * inv0, o[nt][1] * inv0);
        *(uint32_t*)(od + (size_t)8 * DIM + nt * 8 + 2 * tig) =
            pack_h2(o[nt][2] * inv1, o[nt][3] * inv1);
    }
}

// ---------------------------------------------------------------------------
// Launch
// ---------------------------------------------------------------------------
extern "C" void kernel_launch(void* const* d_in, const int* in_sizes, int n_in,
                              void* d_out, int out_size)
{
    (void)in_sizes; (void)n_in; (void)out_size;
    const float* Q  = (const float*)d_in[0];
    const float* K  = (const float*)d_in[1];
    const float* V  = (const float*)d_in[2];
    const int* mask = (const int*)d_in[3];
    const float* Wq = (const float*)d_in[4];
    const float* bq = (const float*)d_in[5];
    const float* Wk = (const float*)d_in[6];
    const float* bk = (const float*)d_in[7];
    const float* Wv = (const float*)d_in[8];
    const float* bv = (const float*)d_in[9];
    const float* Wo = (const float*)d_in[10];
    const float* bo = (const float*)d_in[11];
    float* out = (float*)d_out;

    cudaFuncSetAttribute(qkv_gemm_kernel,
                         cudaFuncAttributeMaxDynamicSharedMemorySize,
                         GEMM_SMEM_BYTES);
    cudaFuncSetAttribute(oproj_gemm_kernel,
                         cudaFuncAttributeMaxDynamicSharedMemorySize,
                         GEMM_SMEM_BYTES);
    cudaFuncSetAttribute(attn_mma_kernel,
                         cudaFuncAttributeMaxDynamicSharedMemorySize,
                         ATTN_SMEM_BYTES);

    // Convert inputs and weights to fp16 (weights transposed, Wq pre-scaled).
    dim3 cigrid(MROWS * DIM / (256 * 8), 3);
    convert_in_kernel<<<cigrid, 256>>>(Q, K, V);
    dim3 cwgrid(32, 32, 4), cwblk(32, 8);
    convert_wt_kernel<<<cwgrid, cwblk>>>(Wq, Wk, Wv, Wo);

    // Batched QKV projections.
    dim3 qkvgrid(DIM / 128, MROWS / 128, 3);
    qkv_gemm_kernel<<<qkvgrid, 256, GEMM_SMEM_BYTES>>>(bq, bk, bv);

    // Attention.
    dim3 agrid(SEQ / 128, NHEAD, BSZ);  // (16, 16, 2)
    attn_mma_kernel<<<agrid, 256, ATTN_SMEM_BYTES>>>(mask);

    // Output projection.
    dim3 ggrid(DIM / 128, MROWS / 128);
    oproj_gemm_kernel<<<ggrid, 256, GEMM_SMEM_BYTES>>>(bo, out);
}

// round 10
// speedup vs baseline: 2.0604x; 1.1447x over previous
#include <cuda_runtime.h>
#include <cuda_fp16.h>
#include <cstdint>

#define BSZ 2
#define SEQ 2048
#define DIM 1024
#define NHEAD 16
#define HDIM 64
#define MROWS (BSZ * SEQ)   // 4096

// Scratch (allocation-free requirement -> __device__ globals), all fp16.
__device__ __half g_hin[(size_t)3 * MROWS * DIM];  // converted inputs Q,K,V
__device__ __half g_hwt[(size_t)4 * DIM * DIM];    // W^T fp16 (Wq pre-scaled)
__device__ __half g_hq[(size_t)MROWS * DIM];       // q proj (scaled)
__device__ __half g_hk[(size_t)MROWS * DIM];       // k proj
__device__ __half g_vt[(size_t)BSZ * DIM * SEQ];   // v proj, transposed [b][dim][s]
__device__ __half g_hctx[(size_t)MROWS * DIM];     // attention output
__device__ uint32_t g_mb[(size_t)SEQ * (SEQ / 32)]; // mask bit-packed, 64 w/row

// 0.125 (1/sqrt(64)) * log2(e): folded into Wq/bq so softmax can use exp2.
#define QSCALE 0.1803368801111137f

__device__ __forceinline__ uint32_t smem_u32(const void* p) {
    uint32_t a;
    asm("{ .reg .u64 t; cvta.to.shared.u64 t, %1; cvt.u32.u64 %0, t; }"
        : "=r"(a) : "l"(p));
    return a;
}

__device__ __forceinline__ void cp_async16(uint32_t dst, const void* src) {
    asm volatile("cp.async.cg.shared.global [%0], [%1], 16;"
                 :: "r"(dst), "l"(src));
}
#define CP_COMMIT() asm volatile("cp.async.commit_group;" ::: "memory")
#define CP_WAIT0()  asm volatile("cp.async.wait_group 0;" ::: "memory")
#define CP_WAIT1()  asm volatile("cp.async.wait_group 1;" ::: "memory")

__device__ __forceinline__ uint32_t pack_h2(float lo, float hi) {
    __half2 h = __floats2half2_rn(lo, hi);
    return *(uint32_t*)&h;
}

__device__ __forceinline__ float ex2(float x) {
    float r;
    asm("ex2.approx.ftz.f32 %0, %1;" : "=f"(r) : "f"(x));
    return r;
}

// ldmatrix x4: loads four 8x8 b16 tiles.
__device__ __forceinline__ void ldsm_x4(uint32_t& r0, uint32_t& r1,
                                        uint32_t& r2, uint32_t& r3,
                                        uint32_t addr) {
    asm volatile("ldmatrix.sync.aligned.m8n8.x4.shared.b16 "
                 "{%0,%1,%2,%3}, [%4];"
                 : "=r"(r0), "=r"(r1), "=r"(r2), "=r"(r3) : "r"(addr));
}

// m16n8k16 fp16 HMMA, fp32 accumulate.
__device__ __forceinline__ void mma_f16(float c[4],
                                        uint32_t a0, uint32_t a1,
                                        uint32_t a2, uint32_t a3,
                                        uint32_t b0, uint32_t b1) {
    asm volatile(
        "mma.sync.aligned.m16n8k16.row.col.f32.f16.f16.f32 "
        "{%0,%1,%2,%3}, {%4,%5,%6,%7}, {%8,%9}, {%0,%1,%2,%3};"
        : "+f"(c[0]), "+f"(c[1]), "+f"(c[2]), "+f"(c[3])
        : "r"(a0), "r"(a1), "r"(a2), "r"(a3), "r"(b0), "r"(b1));
}

// ---------------------------------------------------------------------------
// Input convert: fp32 -> fp16, Q/K/V in one launch (grid.y = 3).
// ---------------------------------------------------------------------------
__global__ __launch_bounds__(256) void convert_in_kernel(
    const float* __restrict__ Q, const float* __restrict__ K,
    const float* __restrict__ V)
{
    const int z = blockIdx.y;
    const float* src = (z == 0) ? Q : (z == 1) ? K : V;
    size_t off = ((size_t)blockIdx.x * 256 + threadIdx.x) * 8;
    float4 v0 = *(const float4*)(src + off);
    float4 v1 = *(const float4*)(src + off + 4);
    __half2* dst = (__half2*)(g_hin + (size_t)z * MROWS * DIM + off);
    uint4 pk;
    pk.x = pack_h2(v0.x, v0.y);
    pk.y = pack_h2(v0.z, v0.w);
    pk.z = pack_h2(v1.x, v1.y);
    pk.w = pack_h2(v1.z, v1.w);
    *(uint4*)dst = pk;
}

// ---------------------------------------------------------------------------
// Mask pack: g_mb[q][k/32] bit k%32 = (mask[q][k] != 0).
// ---------------------------------------------------------------------------
__global__ __launch_bounds__(256) void pack_mask_kernel(
    const int* __restrict__ mask)
{
    int idx = blockIdx.x * 256 + threadIdx.x;   // word index
    const int* src = mask + (size_t)idx * 32;
    uint32_t bits = 0;
#pragma unroll
    for (int u = 0; u < 8; ++u) {
        int4 v = *(const int4*)(src + u * 4);
        bits |= (v.x ? 1u : 0u) << (u * 4);
        bits |= (v.y ? 1u : 0u) << (u * 4 + 1);
        bits |= (v.z ? 1u : 0u) << (u * 4 + 2);
        bits |= (v.w ? 1u : 0u) << (u * 4 + 3);
    }
    g_mb[idx] = bits;
}

// ---------------------------------------------------------------------------
// Weight transpose+convert: g_hwt[z][n][k] = fp16(W[z][k][n] * scale).
// ---------------------------------------------------------------------------
__global__ __launch_bounds__(256) void convert_wt_kernel(
    const float* __restrict__ Wq, const float* __restrict__ Wk,
    const float* __restrict__ Wv, const float* __restrict__ Wo)
{
    __shared__ float t[32][33];
    const int z = blockIdx.z;
    const float* W = (z == 0) ? Wq : (z == 1) ? Wk : (z == 2) ? Wv : Wo;
    const float scale = (z == 0) ? QSCALE : 1.0f;
    __half* WT = g_hwt + (size_t)z * DIM * DIM;
    const int bx = blockIdx.x * 32;   // n
    const int by = blockIdx.y * 32;   // k
    const int x = threadIdx.x, y = threadIdx.y;
#pragma unroll
    for (int j = 0; j < 32; j += 8)
        t[y + j][x] = W[(size_t)(by + y + j) * DIM + bx + x];
    __syncthreads();
#pragma unroll
    for (int j = 0; j < 32; j += 8)
        WT[(size_t)(bx + y + j) * DIM + by + x] =
            __float2half(t[x][y + j] * scale);
}

// ---------------------------------------------------------------------------
// fp16 GEMM: acc[4096,1024] = A @ WT^T (WT is [n][k]), + bias*bscale.
// 128x128 tile, BK=32 (2 k16 steps), cp.async 3-stage, one barrier/chunk,
// ldmatrix fragment loads.
// MODE 0: half row-major out.  MODE 1: half transposed out ([b][dim][s]).
// MODE 2: float row-major out.
// ---------------------------------------------------------------------------
#define PAH 40                               // halves pitch => 80 B
#define SB_OFF (128 * PAH * 2)               // 10240 B: B within stage
#define STAGE_BYTES (2 * 128 * PAH * 2)      // 20480 B
#define OFF_BIAS_B (3 * STAGE_BYTES)         // 61440
#define GEMM_SMEM_BYTES (OFF_BIAS_B + 128 * 4)

__device__ __forceinline__ void gemm_issue_h(
    uint32_t sbase, int s, int ch, const __half* __restrict__ A,
    const __half* __restrict__ WT, int m0, int n0, int tid)
{
    uint32_t sa = sbase + (uint32_t)(s * STAGE_BYTES);
    uint32_t sb = sa + SB_OFF;
    const __half* Ap = A + (size_t)m0 * DIM + ch * 32;
    const __half* Wp = WT + (size_t)n0 * DIM + ch * 32;
#pragma unroll
    for (int u = 0; u < 2; ++u) {
        int i = tid + u * 256;               // 512: 128 rows x 4 chunks
        int row = i >> 2, c16 = i & 3;
        cp_async16(sa + (uint32_t)(row * 80 + c16 * 16),
                   Ap + (size_t)row * DIM + c16 * 8);
        cp_async16(sb + (uint32_t)(row * 80 + c16 * 16),
                   Wp + (size_t)row * DIM + c16 * 8);
    }
}

template <int MODE>
__device__ __forceinline__ void gemm_body_h(
    const __half* __restrict__ A, const __half* __restrict__ WT,
    const float* __restrict__ bias, void* Cout, float bscale, char* smc)
{
    float* sbias = (float*)(smc + OFF_BIAS_B);
    const uint32_t sbase = smem_u32(smc);
    const int tid = threadIdx.x;
    const int wid = tid >> 5, lane = tid & 31;
    const int wm = wid >> 2, wn = wid & 3;
    const int g = lane >> 2, tig = lane & 3;
    const int n0 = blockIdx.x * 128;
    const int m0 = blockIdx.y * 128;

    if (tid < 128) sbias[tid] = bias[n0 + tid] * bscale;

    // ldmatrix per-lane address offsets (A-style and B-style frags).
    const uint32_t afoff = (uint32_t)(
        (wm * 64 + ((lane >> 3) & 1) * 8 + (lane & 7)) * 80 +
        ((lane >> 4) & 1) * 16);
    const uint32_t bfoff = (uint32_t)(
        (wn * 32 + ((lane >> 4) & 1) * 8 + (lane & 7)) * 80 +
        ((lane >> 3) & 1) * 16);

    float c[4][4][4];
#pragma unroll
    for (int mt = 0; mt < 4; ++mt)
#pragma unroll
        for (int nt = 0; nt < 4; ++nt)
#pragma unroll
            for (int q = 0; q < 4; ++q) c[mt][nt][q] = 0.f;

    gemm_issue_h(sbase, 0, 0, A, WT, m0, n0, tid);
    CP_COMMIT();
    gemm_issue_h(sbase, 1, 1, A, WT, m0, n0, tid);
    CP_COMMIT();

    for (int ch = 0; ch < 32; ++ch) {
        if (ch == 31) CP_WAIT0(); else CP_WAIT1();
        __syncthreads();
        if (ch < 30) {
            gemm_issue_h(sbase, (ch + 2) % 3, ch + 2, A, WT, m0, n0, tid);
            CP_COMMIT();
        }

        const uint32_t sAb = sbase + (uint32_t)((ch % 3) * STAGE_BYTES);
        const uint32_t sBb = sAb + SB_OFF;

#pragma unroll
        for (int kk = 0; kk < 2; ++kk) {
            uint32_t af[4][4], bf[4][2];
#pragma unroll
            for (int mt = 0; mt < 4; ++mt)
                ldsm_x4(af[mt][0], af[mt][1], af[mt][2], af[mt][3],
                        sAb + afoff + mt * 1280 + kk * 32);
#pragma unroll
            for (int p = 0; p < 2; ++p)
                ldsm_x4(bf[2 * p][0], bf[2 * p][1],
                        bf[2 * p + 1][0], bf[2 * p + 1][1],
                        sBb + bfoff + p * 1280 + kk * 32);
#pragma unroll
            for (int mt = 0; mt < 4; ++mt)
#pragma unroll
                for (int nt = 0; nt < 4; ++nt)
                    mma_f16(c[mt][nt], af[mt][0], af[mt][1], af[mt][2],
                            af[mt][3], bf[nt][0], bf[nt][1]);
        }
    }

#pragma unroll
    for (int mt = 0; mt < 4; ++mt) {
        int row = m0 + wm * 64 + mt * 16 + g;
#pragma unroll
        for (int nt = 0; nt < 4; ++nt) {
            int col = n0 + wn * 32 + nt * 8 + 2 * tig;
            float b0 = sbias[col - n0], b1 = sbias[col - n0 + 1];
            float v00 = c[mt][nt][0] + b0, v01 = c[mt][nt][1] + b1;
            float v10 = c[mt][nt][2] + b0, v11 = c[mt][nt][3] + b1;
            if (MODE == 0) {
                __half* C = (__half*)Cout;
                *(uint32_t*)(C + (size_t)row * DIM + col) = pack_h2(v00, v01);
                *(uint32_t*)(C + (size_t)(row + 8) * DIM + col) =
                    pack_h2(v10, v11);
            } else if (MODE == 1) {
                __half* VT = (__half*)Cout;   // [b][dim][s]
                int bb = row >> 11, ss = row & 2047;
                VT[((size_t)bb * DIM + col) * SEQ + ss] = __float2half(v00);
                VT[((size_t)bb * DIM + col + 1) * SEQ + ss] = __float2half(v01);
                VT[((size_t)bb * DIM + col) * SEQ + ss + 8] = __float2half(v10);
                VT[((size_t)bb * DIM + col + 1) * SEQ + ss + 8] =
                    __float2half(v11);
            } else {
                float* C = (float*)Cout;
                *(float2*)(C + (size_t)row * DIM + col) = make_float2(v00, v01);
                *(float2*)(C + (size_t)(row + 8) * DIM + col) =
                    make_float2(v10, v11);
            }
        }
    }
}

// Batched QKV projection (grid.z = 3). q gets QSCALE (folded into Wq/bq);
// v is written transposed for the PV B-fragment layout.
__global__ __launch_bounds__(256, 2) void qkv_gemm_kernel(
    const float* __restrict__ bq, const float* __restrict__ bk,
    const float* __restrict__ bv)
{
    extern __shared__ char smc[];
    const int z = blockIdx.z;
    const __half* A = g_hin + (size_t)z * MROWS * DIM;
    const __half* WT = g_hwt + (size_t)z * DIM * DIM;
    if (z == 0)
        gemm_body_h<0>(A, WT, bq, g_hq, QSCALE, smc);
    else if (z == 1)
        gemm_body_h<0>(A, WT, bk, g_hk, 1.0f, smc);
    else
        gemm_body_h<1>(A, WT, bv, g_vt, 1.0f, smc);
}

__global__ __launch_bounds__(256, 2) void oproj_gemm_kernel(
    const float* __restrict__ bias, float* __restrict__ C)
{
    extern __shared__ char smc[];
    gemm_body_h<2>(g_hctx, g_hwt + (size_t)3 * DIM * DIM, bias, C, 1.0f, smc);
}

// ---------------------------------------------------------------------------
// FA2 attention, fp16 MMAs + ldmatrix + bit-packed mask.
// Block = 128 q rows x one head x one batch; warp owns 16 q rows.
// ---------------------------------------------------------------------------
#define APH 72                                // halves pitch => 144 B
#define Q_BYTES (128 * APH * 2)               // 18432
#define KV_V_OFF (64 * APH * 2)               // 9216
#define KV_STAGE_B (2 * 64 * APH * 2)         // 18432
#define ATTN_SMEM_BYTES (Q_BYTES + 2 * KV_STAGE_B)   // 55296

__global__ __launch_bounds__(256, 2) void attn_mma_kernel()
{
    extern __shared__ char smc[];
    const uint32_t sbase = smem_u32(smc);

    const int tid = threadIdx.x;
    const int wid = tid >> 5, lane = tid & 31;
    const int g = lane >> 2, tig = lane & 3;
    const int q0 = blockIdx.x * 128;
    const int h = blockIdx.y;
    const int b = blockIdx.z;

    const __half* qb = g_hq + ((size_t)b * SEQ + q0) * DIM + h * HDIM;
    const __half* kb = g_hk + (size_t)b * SEQ * DIM + h * HDIM;
    const __half* vtb = g_vt + ((size_t)b * DIM + h * HDIM) * SEQ;

    // ldmatrix per-lane address offsets.
    const uint32_t qoff = (uint32_t)(
        (wid * 16 + ((lane >> 3) & 1) * 8 + (lane & 7)) * 144 +
        ((lane >> 4) & 1) * 16);
    const uint32_t bfoff = (uint32_t)(
        (((lane >> 4) & 1) * 8 + (lane & 7)) * 144 +
        ((lane >> 3) & 1) * 16);

    // Prologue: stage Q (128x64) + K/V tile 0.
#pragma unroll
    for (int u = 0; u < 4; ++u) {
        int i = tid + u * 256;               // 1024: 128 rows x 8 chunks
        int row = i >> 3, c16 = i & 7;
        cp_async16(sbase + (uint32_t)(row * 144 + c16 * 16),
                   qb + (size_t)row * DIM + c16 * 8);
    }
    {
        uint32_t kst = sbase + Q_BYTES;
        uint32_t vst = kst + KV_V_OFF;
#pragma unroll
        for (int u = 0; u < 2; ++u) {
            int i = tid + u * 256;           // 512: 64 rows x 8 chunks
            int row = i >> 3, c16 = i & 7;
            cp_async16(kst + (uint32_t)(row * 144 + c16 * 16),
                       kb + (size_t)row * DIM + c16 * 8);
            cp_async16(vst + (uint32_t)(row * 144 + c16 * 16),
                       vtb + (size_t)row * SEQ + c16 * 8);
        }
    }
    CP_COMMIT();

    const int r0 = wid * 16 + g;
    float m0 = -1e30f, m1 = -1e30f, l0 = 0.f, l1 = 0.f;
    float o[8][4];
#pragma unroll
    for (int nt = 0; nt < 8; ++nt)
#pragma unroll
        for (int q = 0; q < 4; ++q) o[nt][q] = 0.f;

    // Bit-packed mask rows for this thread's two q rows (64 words/row).
    const uint32_t* bmr0 = g_mb + (size_t)(q0 + r0) * (SEQ / 32);
    const uint32_t* bmr1 = bmr0 + 8 * (SEQ / 32);

    for (int kt = 0; kt < SEQ / 64; ++kt) {
        const int kg0 = kt * 64;

        // Mask bits for this tile (hoisted above the wait; L2-resident).
        uint2 w0 = *(const uint2*)(bmr0 + (kg0 >> 5));
        uint2 w1 = *(const uint2*)(bmr1 + (kg0 >> 5));

        CP_WAIT0();
        __syncthreads();

        // Prefetch next K/V tile.
        if (kt < SEQ / 64 - 1) {
            int s = (kt + 1) & 1;
            int kg = (kt + 1) * 64;
            uint32_t kst = sbase + Q_BYTES + (uint32_t)(s * KV_STAGE_B);
            uint32_t vst = kst + KV_V_OFF;
#pragma unroll
            for (int u = 0; u < 2; ++u) {
                int i = tid + u * 256;
                int row = i >> 3, c16 = i & 7;
                cp_async16(kst + (uint32_t)(row * 144 + c16 * 16),
                           kb + (size_t)(kg + row) * DIM + c16 * 8);
                cp_async16(vst + (uint32_t)(row * 144 + c16 * 16),
                           vtb + (size_t)row * SEQ + kg + c16 * 8);
            }
            CP_COMMIT();
        }

        const uint32_t kbase_s = sbase + Q_BYTES
                                 + (uint32_t)((kt & 1) * KV_STAGE_B);
        const uint32_t vbase_s = kbase_s + KV_V_OFF;

        // S = Q @ K^T : 4 k16 steps, 8 n-tiles, S in registers.
        float c[8][4];
#pragma unroll
        for (int nt = 0; nt < 8; ++nt)
#pragma unroll
            for (int q = 0; q < 4; ++q) c[nt][q] = 0.f;

#pragma unroll
        for (int kk = 0; kk < 4; ++kk) {
            uint32_t a0, a1, a2, a3;
            ldsm_x4(a0, a1, a2, a3, sbase + qoff + kk * 32);
#pragma unroll
            for (int p = 0; p < 4; ++p) {
                uint32_t b0, b1, b2, b3;
                ldsm_x4(b0, b1, b2, b3,
                        kbase_s + bfoff + p * 2304 + kk * 32);
                mma_f16(c[2 * p], a0, a1, a2, a3, b0, b1);
                mma_f16(c[2 * p + 1], a0, a1, a2, a3, b2, b3);
            }
        }

        // Mask (bit tests) + row max (scores in log2 units).
        float mx0 = -1e30f, mx1 = -1e30f;
#pragma unroll
        for (int nt = 0; nt < 8; ++nt) {
            uint32_t wa = (nt < 4) ? w0.x : w0.y;
            uint32_t wb = (nt < 4) ? w1.x : w1.y;
            int sh = (nt & 3) * 8 + 2 * tig;
            uint32_t ta = wa >> sh, tb = wb >> sh;
            c[nt][0] = (ta & 1u) ? c[nt][0] : -1e30f;
            c[nt][1] = (ta & 2u) ? c[nt][1] : -1e30f;
            c[nt][2] = (tb & 1u) ? c[nt][2] : -1e30f;
            c[nt][3] = (tb & 2u) ? c[nt][3] : -1e30f;
            mx0 = fmaxf(mx0, fmaxf(c[nt][0], c[nt][1]));
            mx1 = fmaxf(mx1, fmaxf(c[nt][2], c[nt][3]));
        }
        mx0 = fmaxf(mx0, __shfl_xor_sync(0xffffffffu, mx0, 1));
        mx0 = fmaxf(mx0, __shfl_xor_sync(0xffffffffu, mx0, 2));
        mx1 = fmaxf(mx1, __shfl_xor_sync(0xffffffffu, mx1, 1));
        mx1 = fmaxf(mx1, __shfl_xor_sync(0xffffffffu, mx1, 2));

        float mn0 = fmaxf(m0, mx0), mn1 = fmaxf(m1, mx1);
        float al0 = ex2(m0 - mn0), al1 = ex2(m1 - mn1);
        float s0 = 0.f, s1 = 0.f;
#pragma unroll
        for (int nt = 0; nt < 8; ++nt) {
            float p0 = ex2(c[nt][0] - mn0);
            float p1 = ex2(c[nt][1] - mn0);
            float p2 = ex2(c[nt][2] - mn1);
            float p3 = ex2(c[nt][3] - mn1);
            s0 += p0 + p1;
            s1 += p2 + p3;
            c[nt][0] = p0; c[nt][1] = p1; c[nt][2] = p2; c[nt][3] = p3;
        }
        s0 += __shfl_xor_sync(0xffffffffu, s0, 1);
        s0 += __shfl_xor_sync(0xffffffffu, s0, 2);
        s1 += __shfl_xor_sync(0xffffffffu, s1, 1);
        s1 += __shfl_xor_sync(0xffffffffu, s1, 2);
        l0 = l0 * al0 + s0;
        l1 = l1 * al1 + s1;
        m0 = mn0; m1 = mn1;

#pragma unroll
        for (int nt = 0; nt < 8; ++nt) {
            o[nt][0] *= al0; o[nt][1] *= al0;
            o[nt][2] *= al1; o[nt][3] *= al1;
        }

        // O += P @ V: A-frags come straight from the S C-frags (k16).
#pragma unroll
        for (int kk = 0; kk < 4; ++kk) {
            uint32_t a0 = pack_h2(c[2 * kk][0], c[2 * kk][1]);
            uint32_t a1 = pack_h2(c[2 * kk][2], c[2 * kk][3]);
            uint32_t a2 = pack_h2(c[2 * kk + 1][0], c[2 * kk + 1][1]);
            uint32_t a3 = pack_h2(c[2 * kk + 1][2], c[2 * kk + 1][3]);
#pragma unroll
            for (int p = 0; p < 4; ++p) {
                uint32_t b0, b1, b2, b3;
                ldsm_x4(b0, b1, b2, b3,
                        vbase_s + bfoff + p * 2304 + kk * 32);
                mma_f16(o[2 * p], a0, a1, a2, a3, b0, b1);
                mma_f16(o[2 * p + 1], a0, a1, a2, a3, b2, b3);
            }
        }
    }

    // Final normalize + store fp16 (merged-head layout).
    float inv0 = 1.f / l0, inv1 = 1.f / l1;
    __half* od = g_hctx + ((size_t)b * SEQ + q0 + r0) * DIM + h * HDIM;
#pragma unroll
    for (int nt = 0; nt < 8; ++nt) {
        *(uint32_t*)(od + nt * 8 + 2 * tig) =
            pack_h2(o[nt][0] * inv0, o[nt][1] * inv0);
        *(uint32_t*)(od + (size_t)8 * DIM + nt * 8 + 2 * tig) =
            pack_h2(o[nt][2] * inv1, o[nt][3] * inv1);
    }
}

// ---------------------------------------------------------------------------
// Launch
// ---------------------------------------------------------------------------
extern "C" void kernel_launch(void* const* d_in, const int* in_sizes, int n_in,
                              void* d_out, int out_size)
{
    (void)in_sizes; (void)n_in; (void)out_size;
    const float* Q  = (const float*)d_in[0];
    const float* K  = (const float*)d_in[1];
    const float* V  = (const float*)d_in[2];
    const int* mask = (const int*)d_in[3];
    const float* Wq = (const float*)d_in[4];
    const float* bq = (const float*)d_in[5];
    const float* Wk = (const float*)d_in[6];
    const float* bk = (const float*)d_in[7];
    const float* Wv = (const float*)d_in[8];
    const float* bv = (const float*)d_in[9];
    const float* Wo = (const float*)d_in[10];
    const float* bo = (const float*)d_in[11];
    float* out = (float*)d_out;

    cudaFuncSetAttribute(qkv_gemm_kernel,
                         cudaFuncAttributeMaxDynamicSharedMemorySize,
                         GEMM_SMEM_BYTES);
    cudaFuncSetAttribute(oproj_gemm_kernel,
                         cudaFuncAttributeMaxDynamicSharedMemorySize,
                         GEMM_SMEM_BYTES);
    cudaFuncSetAttribute(attn_mma_kernel,
                         cudaFuncAttributeMaxDynamicSharedMemorySize,
                         ATTN_SMEM_BYTES);

    // Convert inputs and weights to fp16; pack the mask to bits.
    dim3 cigrid(MROWS * DIM / (256 * 8), 3);
    convert_in_kernel<<<cigrid, 256>>>(Q, K, V);
    pack_mask_kernel<<<SEQ * (SEQ / 32) / 256, 256>>>(mask);
    dim3 cwgrid(32, 32, 4), cwblk(32, 8);
    convert_wt_kernel<<<cwgrid, cwblk>>>(Wq, Wk, Wv, Wo);

    // Batched QKV projections.
    dim3 qkvgrid(DIM / 128, MROWS / 128, 3);
    qkv_gemm_kernel<<<qkvgrid, 256, GEMM_SMEM_BYTES>>>(bq, bk, bv);

    // Attention.
    dim3 agrid(SEQ / 128, NHEAD, BSZ);  // (16, 16, 2)
    attn_mma_kernel<<<agrid, 256, ATTN_SMEM_BYTES>>>();

    // Output projection.
    dim3 ggrid(DIM / 128, MROWS / 128);
    oproj_gemm_kernel<<<ggrid, 256, GEMM_SMEM_BYTES>>>(bo, out);
}